// round 3
// baseline (speedup 1.0000x reference)
#include <cuda_runtime.h>
#include <cstdint>

#define EMBED 2048
#define KVDIM 512
#define SEQ   2048
#define BATCH 2
#define HEADS 16
#define HD    128
#define ROWS_TOTAL (BATCH * SEQ)   // 4096

// -------- scratch (allocation-free: __device__ globals) --------
__device__ float g_Q [ROWS_TOTAL * EMBED];   // 33.5 MB
__device__ float g_K [ROWS_TOTAL * KVDIM];   //  8.4 MB
__device__ float g_V [ROWS_TOTAL * KVDIM];   //  8.4 MB
__device__ float g_AO[ROWS_TOTAL * EMBED];   // 33.5 MB

// ==================== SGEMM: C = A @ W + bias ====================
#define BM 128
#define BN 128
#define BK 16
#define TM 8
#define TN 8

__global__ __launch_bounds__(256, 2) void sgemm_bias(
    const float* __restrict__ A, const float* __restrict__ W,
    const float* __restrict__ bias, float* __restrict__ C,
    int M, int N, int K)
{
    __shared__ float As[BK][BM];   // transposed A tile
    __shared__ float Bs[BK][BN];

    const int tid = threadIdx.x;
    const int bm = blockIdx.y * BM;
    const int bn = blockIdx.x * BN;

    const int a_row = tid >> 2;          // 0..63
    const int a_col = (tid & 3) << 2;    // 0,4,8,12
    const int b_row = tid >> 5;          // 0..7
    const int b_col = (tid & 31) << 2;   // 0..124

    const int tx = (tid & 15) << 3;      // col offset 0..120
    const int ty = (tid >> 4) << 3;      // row offset 0..120

    float acc[TM][TN];
#pragma unroll
    for (int i = 0; i < TM; i++)
#pragma unroll
        for (int j = 0; j < TN; j++) acc[i][j] = 0.f;

    const int KT = K / BK;

    const float* aP  = A + (size_t)(bm + a_row) * K + a_col;
    const float* aP2 = aP + (size_t)64 * K;
    const float* bP  = W + (size_t)b_row * N + bn + b_col;
    const float* bP2 = bP + (size_t)8 * N;

    float4 ra0 = *(const float4*)aP;
    float4 ra1 = *(const float4*)aP2;
    float4 rb0 = *(const float4*)bP;
    float4 rb1 = *(const float4*)bP2;

    for (int kt = 0; kt < KT; kt++) {
        As[a_col + 0][a_row]      = ra0.x; As[a_col + 1][a_row]      = ra0.y;
        As[a_col + 2][a_row]      = ra0.z; As[a_col + 3][a_row]      = ra0.w;
        As[a_col + 0][a_row + 64] = ra1.x; As[a_col + 1][a_row + 64] = ra1.y;
        As[a_col + 2][a_row + 64] = ra1.z; As[a_col + 3][a_row + 64] = ra1.w;
        *(float4*)&Bs[b_row][b_col]     = rb0;
        *(float4*)&Bs[b_row + 8][b_col] = rb1;
        __syncthreads();

        if (kt + 1 < KT) {
            ra0 = *(const float4*)(aP  + (size_t)(kt + 1) * BK);
            ra1 = *(const float4*)(aP2 + (size_t)(kt + 1) * BK);
            rb0 = *(const float4*)(bP  + (size_t)(kt + 1) * BK * N);
            rb1 = *(const float4*)(bP2 + (size_t)(kt + 1) * BK * N);
        }

#pragma unroll
        for (int k = 0; k < BK; k++) {
            float a[TM], bb[TN];
            *(float4*)&a[0]  = *(float4*)&As[k][ty];
            *(float4*)&a[4]  = *(float4*)&As[k][ty + 4];
            *(float4*)&bb[0] = *(float4*)&Bs[k][tx];
            *(float4*)&bb[4] = *(float4*)&Bs[k][tx + 4];
#pragma unroll
            for (int i = 0; i < TM; i++)
#pragma unroll
                for (int j = 0; j < TN; j++)
                    acc[i][j] = fmaf(a[i], bb[j], acc[i][j]);
        }
        __syncthreads();
    }

    float bv[TN];
#pragma unroll
    for (int j = 0; j < TN; j++) bv[j] = bias[bn + tx + j];

#pragma unroll
    for (int i = 0; i < TM; i++) {
        float* cp = C + (size_t)(bm + ty + i) * N + bn + tx;
        float4 o0 = make_float4(acc[i][0] + bv[0], acc[i][1] + bv[1],
                                acc[i][2] + bv[2], acc[i][3] + bv[3]);
        float4 o1 = make_float4(acc[i][4] + bv[4], acc[i][5] + bv[5],
                                acc[i][6] + bv[6], acc[i][7] + bv[7]);
        *(float4*)cp       = o0;
        *(float4*)(cp + 4) = o1;
    }
}

// ==================== Flash attention (fp32, causal, GQA) ====================
// Block: 256 threads (8 warps). Tile: 64 q-rows x 64 k-cols, d=128.
// warp w owns q rows r0..r0+7; lane owns key cols {lane, lane+32} for scores
// and output cols lane*4..lane*4+3 for PV.
// smem (dynamic, 114944 B):
//   Qs  float4[64][32]           @ float ofs 0
//   Ks  float4[64][32] swizzled  @ 8192   (col c stored at c ^ (n&31))
//   Vs  float4[64][32]           @ 16384
//   Ps  float [64][65]           @ 24576
#define ATT_SMEM_BYTES 114944

__global__ __launch_bounds__(256) void gqa_attn(
    const float* __restrict__ Q, const float* __restrict__ Kbuf,
    const float* __restrict__ Vbuf, float* __restrict__ AO)
{
    extern __shared__ float sm[];
    float4* Qs = (float4*)sm;
    float4* Ks = (float4*)(sm + 8192);
    float4* Vs = (float4*)(sm + 16384);
    float*  Ps = sm + 24576;

    const int tid  = threadIdx.x;
    const int lane = tid & 31;
    const int warp = tid >> 5;
    const int qb   = blockIdx.x;          // q tile index (0..31)
    const int b    = blockIdx.y >> 4;
    const int h    = blockIdx.y & 15;
    const int g    = h >> 2;              // KV group (REPEATS = 4)
    const float scale = 0.08838834764831845f;  // 1/sqrt(128)

    // load Q tile [64][128]
#pragma unroll
    for (int i = 0; i < 8; i++) {
        int idx = tid + i * 256;
        int r = idx >> 5, c = idx & 31;
        Qs[r * 32 + c] = *(const float4*)(
            Q + (size_t)(b * SEQ + (qb << 6) + r) * EMBED + h * HD + (c << 2));
    }

    const int r0 = warp << 3;
    const int n0 = lane, n1 = lane + 32;

    float m_r[8], l_r[8];
    float4 o[8];
#pragma unroll
    for (int i = 0; i < 8; i++) {
        m_r[i] = -1e30f; l_r[i] = 0.f;
        o[i] = make_float4(0.f, 0.f, 0.f, 0.f);
    }
    __syncthreads();

    for (int kb = 0; kb <= qb; kb++) {
        // load K (swizzled) and V tiles
#pragma unroll
        for (int i = 0; i < 8; i++) {
            int idx = tid + i * 256;
            int n = idx >> 5, c = idx & 31;
            size_t base = (size_t)(b * SEQ + (kb << 6) + n) * KVDIM + g * HD + (c << 2);
            Ks[n * 32 + (c ^ (n & 31))] = *(const float4*)(Kbuf + base);
            Vs[n * 32 + c]              = *(const float4*)(Vbuf + base);
        }
        __syncthreads();

        // scores: s0 -> key n0, s1 -> key n1
        float s0[8], s1[8];
#pragma unroll
        for (int i = 0; i < 8; i++) { s0[i] = 0.f; s1[i] = 0.f; }

#pragma unroll 4
        for (int d4 = 0; d4 < 32; d4++) {
            float4 ka = Ks[n0 * 32 + (d4 ^ lane)];
            float4 kc = Ks[n1 * 32 + (d4 ^ lane)];
#pragma unroll
            for (int i = 0; i < 8; i++) {
                float4 q4 = Qs[(r0 + i) * 32 + d4];
                s0[i] = fmaf(q4.x, ka.x, fmaf(q4.y, ka.y,
                         fmaf(q4.z, ka.z, fmaf(q4.w, ka.w, s0[i]))));
                s1[i] = fmaf(q4.x, kc.x, fmaf(q4.y, kc.y,
                         fmaf(q4.z, kc.z, fmaf(q4.w, kc.w, s1[i]))));
            }
        }

        // online softmax update
        const bool diag = (kb == qb);
#pragma unroll
        for (int i = 0; i < 8; i++) {
            float v0 = s0[i] * scale, v1 = s1[i] * scale;
            if (diag) {
                int qg = (qb << 6) + r0 + i;
                int kg = (kb << 6);
                if (kg + n0 > qg) v0 = -1e30f;
                if (kg + n1 > qg) v1 = -1e30f;
            }
            float mx = fmaxf(v0, v1);
#pragma unroll
            for (int off = 16; off > 0; off >>= 1)
                mx = fmaxf(mx, __shfl_xor_sync(0xffffffffu, mx, off));
            float mnew = fmaxf(m_r[i], mx);
            float p0   = __expf(v0 - mnew);
            float p1   = __expf(v1 - mnew);
            float corr = __expf(m_r[i] - mnew);
            m_r[i] = mnew;
            float rs = p0 + p1;
#pragma unroll
            for (int off = 16; off > 0; off >>= 1)
                rs += __shfl_xor_sync(0xffffffffu, rs, off);
            l_r[i] = l_r[i] * corr + rs;
            o[i].x *= corr; o[i].y *= corr; o[i].z *= corr; o[i].w *= corr;
            Ps[(r0 + i) * 65 + n0] = p0;
            Ps[(r0 + i) * 65 + n1] = p1;
        }
        __syncwarp();   // Ps rows are warp-private

        // O += P @ V   (lane owns cols lane*4..+3)
#pragma unroll 2
        for (int n = 0; n < 64; n++) {
            float4 v4 = Vs[n * 32 + lane];
#pragma unroll
            for (int i = 0; i < 8; i++) {
                float p = Ps[(r0 + i) * 65 + n];
                o[i].x = fmaf(p, v4.x, o[i].x);
                o[i].y = fmaf(p, v4.y, o[i].y);
                o[i].z = fmaf(p, v4.z, o[i].z);
                o[i].w = fmaf(p, v4.w, o[i].w);
            }
        }
        __syncthreads();   // before K/V overwrite next iter
    }

    // normalize + store: AO[b, t, h*128 + c]
#pragma unroll
    for (int i = 0; i < 8; i++) {
        float inv = 1.0f / l_r[i];
        float4 r = o[i];
        r.x *= inv; r.y *= inv; r.z *= inv; r.w *= inv;
        *(float4*)(AO + (size_t)(b * SEQ + (qb << 6) + r0 + i) * EMBED
                      + h * HD + (lane << 2)) = r;
    }
}

// ==================== launch ====================
extern "C" void kernel_launch(void* const* d_in, const int* in_sizes, int n_in,
                              void* d_out, int out_size)
{
    const float* x  = (const float*)d_in[0];
    const float* Wq = (const float*)d_in[1];
    const float* bq = (const float*)d_in[2];
    const float* Wk = (const float*)d_in[3];
    const float* bk = (const float*)d_in[4];
    const float* Wv = (const float*)d_in[5];
    const float* bv = (const float*)d_in[6];
    const float* Wo = (const float*)d_in[7];
    const float* bo = (const float*)d_in[8];
    float* out = (float*)d_out;

    float *gq, *gk, *gv, *gao;
    cudaGetSymbolAddress((void**)&gq,  g_Q);
    cudaGetSymbolAddress((void**)&gk,  g_K);
    cudaGetSymbolAddress((void**)&gv,  g_V);
    cudaGetSymbolAddress((void**)&gao, g_AO);

    cudaFuncSetAttribute(gqa_attn, cudaFuncAttributeMaxDynamicSharedMemorySize,
                         ATT_SMEM_BYTES);

    dim3 blk(256);
    sgemm_bias<<<dim3(EMBED / BN, ROWS_TOTAL / BM), blk>>>(
        x, Wq, bq, gq, ROWS_TOTAL, EMBED, EMBED);
    sgemm_bias<<<dim3(KVDIM / BN, ROWS_TOTAL / BM), blk>>>(
        x, Wk, bk, gk, ROWS_TOTAL, KVDIM, EMBED);
    sgemm_bias<<<dim3(KVDIM / BN, ROWS_TOTAL / BM), blk>>>(
        x, Wv, bv, gv, ROWS_TOTAL, KVDIM, EMBED);

    gqa_attn<<<dim3(SEQ / 64, BATCH * HEADS), blk, ATT_SMEM_BYTES>>>(
        gq, gk, gv, gao);

    sgemm_bias<<<dim3(EMBED / BN, ROWS_TOTAL / BM), blk>>>(
        gao, Wo, bo, out, ROWS_TOTAL, EMBED, EMBED);
}

// round 4
// speedup vs baseline: 1.6490x; 1.6490x over previous
#include <cuda_runtime.h>
#include <cstdint>

#define EMBED 2048
#define KVDIM 512
#define SEQ   2048
#define BATCH 2
#define HEADS 16
#define HD    128
#define ROWS_TOTAL (BATCH * SEQ)   // 4096

// -------- scratch (allocation-free: __device__ globals) --------
__device__ float g_Q [ROWS_TOTAL * EMBED];
__device__ float g_K [ROWS_TOTAL * KVDIM];
__device__ float g_V [ROWS_TOTAL * KVDIM];
__device__ float g_AO[ROWS_TOTAL * EMBED];

// ==================== TF32 tensor-core GEMM: C = A @ W + bias ====================
// Block tile 128x128x32, 256 threads = 8 warps (2 m x 4 n), warp tile 64x32.
// mma.sync.m16n8k8 tf32: per warp per k-step: 4 m-tiles x 4 n-tiles.
// smem (dynamic 71680 B, uint32 units):
//   As[2][128][36]  m-major, pad 4  -> frag banks (4m+k)%32 unique
//   Bs[2][32][136]  k-major, pad 8  -> frag banks (8k+n)%32 unique
#define G_ASTRIDE 36
#define G_ABUF    (128 * G_ASTRIDE)        // 4608
#define G_BSTRIDE 136
#define G_BBUF    (32 * G_BSTRIDE)         // 4352
#define G_SMEM_BYTES ((2 * G_ABUF + 2 * G_BBUF) * 4)   // 71680

__device__ __forceinline__ uint32_t f2tf32(float f) {
    uint32_t u;
    asm("cvt.rna.tf32.f32 %0, %1;" : "=r"(u) : "f"(f));
    return u;
}

__device__ __forceinline__ void mma_tf32(float* c, const uint32_t* a, const uint32_t* b) {
    asm volatile(
        "mma.sync.aligned.m16n8k8.row.col.f32.tf32.tf32.f32 "
        "{%0,%1,%2,%3}, {%4,%5,%6,%7}, {%8,%9}, {%0,%1,%2,%3};"
        : "+f"(c[0]), "+f"(c[1]), "+f"(c[2]), "+f"(c[3])
        : "r"(a[0]), "r"(a[1]), "r"(a[2]), "r"(a[3]), "r"(b[0]), "r"(b[1]));
}

__global__ __launch_bounds__(256) void gemm_tf32(
    const float* __restrict__ A, const float* __restrict__ W,
    const float* __restrict__ bias, float* __restrict__ C,
    int N, int K)
{
    extern __shared__ uint32_t sm[];
    uint32_t* As = sm;                   // [2][128][36]
    uint32_t* Bs = sm + 2 * G_ABUF;      // [2][32][136]

    const int tid  = threadIdx.x;
    const int lane = tid & 31;
    const int warp = tid >> 5;
    const int wm   = (warp >> 2) * 64;   // 0 or 64
    const int wn   = (warp & 3) * 32;    // 0,32,64,96
    const int g    = lane >> 2;          // 0..7
    const int tq   = lane & 3;           // 0..3

    const int bm = blockIdx.y * 128;
    const int bn = blockIdx.x * 128;
    const int KT = K / 32;

    // global load mapping
    const int a_row = tid >> 3;          // 0..31 (4 row-blocks of 32)
    const int a_c4  = (tid & 7) << 2;    // 0..28
    const int b_k   = tid >> 6;          // 0..3 (4 k-blocks of 8... actually tid>>6: 0..3)
    const int b_n4  = (tid & 63) << 2;   // hmm -> redo below

    // B mapping: 1024 float4 / 256 thr = 4 each: idx = i*256+tid, k = idx>>5, n4=(idx&31)*4
    const int bk0 = tid >> 5;            // 0..7, step 8 per i
    const int bn4 = (tid & 31) << 2;     // 0..124

    const float* aG = A + (size_t)(bm + a_row) * K + a_c4;
    const float* bG = W + (size_t)bk0 * N + bn + bn4;

    float acc[4][4][4];
#pragma unroll
    for (int mt = 0; mt < 4; mt++)
#pragma unroll
        for (int nt = 0; nt < 4; nt++)
#pragma unroll
            for (int i = 0; i < 4; i++) acc[mt][nt][i] = 0.f;

    float4 ra[4], rb[4];

    // prime: load tile 0 into regs
#pragma unroll
    for (int i = 0; i < 4; i++) ra[i] = *(const float4*)(aG + (size_t)(i * 32) * K);
#pragma unroll
    for (int i = 0; i < 4; i++) rb[i] = *(const float4*)(bG + (size_t)(i * 8) * N);

    // store tile 0 into buf 0
    {
        uint32_t* ap = As + a_row * G_ASTRIDE + a_c4;
#pragma unroll
        for (int i = 0; i < 4; i++) {
            uint32_t* p = ap + i * 32 * G_ASTRIDE;
            p[0] = f2tf32(ra[i].x); p[1] = f2tf32(ra[i].y);
            p[2] = f2tf32(ra[i].z); p[3] = f2tf32(ra[i].w);
        }
        uint32_t* bp = Bs + bk0 * G_BSTRIDE + bn4;
#pragma unroll
        for (int i = 0; i < 4; i++) {
            uint32_t* p = bp + i * 8 * G_BSTRIDE;
            p[0] = f2tf32(rb[i].x); p[1] = f2tf32(rb[i].y);
            p[2] = f2tf32(rb[i].z); p[3] = f2tf32(rb[i].w);
        }
    }
    __syncthreads();

    int buf = 0;
    for (int kt = 0; kt < KT; kt++) {
        if (kt + 1 < KT) {
            const float* aN = aG + (kt + 1) * 32;
            const float* bN = bG + (size_t)(kt + 1) * 32 * N;
#pragma unroll
            for (int i = 0; i < 4; i++) ra[i] = *(const float4*)(aN + (size_t)(i * 32) * K);
#pragma unroll
            for (int i = 0; i < 4; i++) rb[i] = *(const float4*)(bN + (size_t)(i * 8) * N);
        }

        // compute on buf
        const uint32_t* Ab = As + buf * G_ABUF + (wm + g) * G_ASTRIDE;
        const uint32_t* Bb = Bs + buf * G_BBUF + wn + g;
#pragma unroll
        for (int ks = 0; ks < 4; ks++) {
            uint32_t af[4][4], bf[4][2];
#pragma unroll
            for (int mt = 0; mt < 4; mt++) {
                const uint32_t* p = Ab + mt * 16 * G_ASTRIDE + ks * 8 + tq;
                af[mt][0] = p[0];
                af[mt][1] = p[8 * G_ASTRIDE];
                af[mt][2] = p[4];
                af[mt][3] = p[8 * G_ASTRIDE + 4];
            }
#pragma unroll
            for (int nt = 0; nt < 4; nt++) {
                const uint32_t* p = Bb + (ks * 8 + tq) * G_BSTRIDE + nt * 8;
                bf[nt][0] = p[0];
                bf[nt][1] = p[4 * G_BSTRIDE];
            }
#pragma unroll
            for (int mt = 0; mt < 4; mt++)
#pragma unroll
                for (int nt = 0; nt < 4; nt++)
                    mma_tf32(acc[mt][nt], af[mt], bf[nt]);
        }

        if (kt + 1 < KT) {
            uint32_t* ap = As + (buf ^ 1) * G_ABUF + a_row * G_ASTRIDE + a_c4;
#pragma unroll
            for (int i = 0; i < 4; i++) {
                uint32_t* p = ap + i * 32 * G_ASTRIDE;
                p[0] = f2tf32(ra[i].x); p[1] = f2tf32(ra[i].y);
                p[2] = f2tf32(ra[i].z); p[3] = f2tf32(ra[i].w);
            }
            uint32_t* bp = Bs + (buf ^ 1) * G_BBUF + bk0 * G_BSTRIDE + bn4;
#pragma unroll
            for (int i = 0; i < 4; i++) {
                uint32_t* p = bp + i * 8 * G_BSTRIDE;
                p[0] = f2tf32(rb[i].x); p[1] = f2tf32(rb[i].y);
                p[2] = f2tf32(rb[i].z); p[3] = f2tf32(rb[i].w);
            }
        }
        __syncthreads();
        buf ^= 1;
    }

    // epilogue: C[m][n] = acc + bias[n]
#pragma unroll
    for (int nt = 0; nt < 4; nt++) {
        int n0 = bn + wn + nt * 8 + tq * 2;
        float bv0 = bias[n0], bv1 = bias[n0 + 1];
#pragma unroll
        for (int mt = 0; mt < 4; mt++) {
            int m0 = bm + wm + mt * 16 + g;
            float2 r0 = make_float2(acc[mt][nt][0] + bv0, acc[mt][nt][1] + bv1);
            float2 r1 = make_float2(acc[mt][nt][2] + bv0, acc[mt][nt][3] + bv1);
            *(float2*)(C + (size_t)m0 * N + n0)       = r0;
            *(float2*)(C + (size_t)(m0 + 8) * N + n0) = r1;
        }
    }
}

// ==================== Flash attention (fp32, causal, GQA) ====================
#define ATT_SMEM_BYTES 114944

__global__ __launch_bounds__(256) void gqa_attn(
    const float* __restrict__ Q, const float* __restrict__ Kbuf,
    const float* __restrict__ Vbuf, float* __restrict__ AO)
{
    extern __shared__ float smf[];
    float4* Qs = (float4*)smf;
    float4* Ks = (float4*)(smf + 8192);
    float4* Vs = (float4*)(smf + 16384);
    float*  Ps = smf + 24576;

    const int tid  = threadIdx.x;
    const int lane = tid & 31;
    const int warp = tid >> 5;
    const int qb   = blockIdx.x;
    const int b    = blockIdx.y >> 4;
    const int h    = blockIdx.y & 15;
    const int g    = h >> 2;
    const float scale = 0.08838834764831845f;

#pragma unroll
    for (int i = 0; i < 8; i++) {
        int idx = tid + i * 256;
        int r = idx >> 5, c = idx & 31;
        Qs[r * 32 + c] = *(const float4*)(
            Q + (size_t)(b * SEQ + (qb << 6) + r) * EMBED + h * HD + (c << 2));
    }

    const int r0 = warp << 3;
    const int n0 = lane, n1 = lane + 32;

    float m_r[8], l_r[8];
    float4 o[8];
#pragma unroll
    for (int i = 0; i < 8; i++) {
        m_r[i] = -1e30f; l_r[i] = 0.f;
        o[i] = make_float4(0.f, 0.f, 0.f, 0.f);
    }
    __syncthreads();

    for (int kb = 0; kb <= qb; kb++) {
#pragma unroll
        for (int i = 0; i < 8; i++) {
            int idx = tid + i * 256;
            int n = idx >> 5, c = idx & 31;
            size_t base = (size_t)(b * SEQ + (kb << 6) + n) * KVDIM + g * HD + (c << 2);
            Ks[n * 32 + (c ^ (n & 31))] = *(const float4*)(Kbuf + base);
            Vs[n * 32 + c]              = *(const float4*)(Vbuf + base);
        }
        __syncthreads();

        float s0[8], s1[8];
#pragma unroll
        for (int i = 0; i < 8; i++) { s0[i] = 0.f; s1[i] = 0.f; }

#pragma unroll 4
        for (int d4 = 0; d4 < 32; d4++) {
            float4 ka = Ks[n0 * 32 + (d4 ^ lane)];
            float4 kc = Ks[n1 * 32 + (d4 ^ lane)];
#pragma unroll
            for (int i = 0; i < 8; i++) {
                float4 q4 = Qs[(r0 + i) * 32 + d4];
                s0[i] = fmaf(q4.x, ka.x, fmaf(q4.y, ka.y,
                         fmaf(q4.z, ka.z, fmaf(q4.w, ka.w, s0[i]))));
                s1[i] = fmaf(q4.x, kc.x, fmaf(q4.y, kc.y,
                         fmaf(q4.z, kc.z, fmaf(q4.w, kc.w, s1[i]))));
            }
        }

        const bool diag = (kb == qb);
#pragma unroll
        for (int i = 0; i < 8; i++) {
            float v0 = s0[i] * scale, v1 = s1[i] * scale;
            if (diag) {
                int qg = (qb << 6) + r0 + i;
                int kg = (kb << 6);
                if (kg + n0 > qg) v0 = -1e30f;
                if (kg + n1 > qg) v1 = -1e30f;
            }
            float mx = fmaxf(v0, v1);
#pragma unroll
            for (int off = 16; off > 0; off >>= 1)
                mx = fmaxf(mx, __shfl_xor_sync(0xffffffffu, mx, off));
            float mnew = fmaxf(m_r[i], mx);
            float p0   = __expf(v0 - mnew);
            float p1   = __expf(v1 - mnew);
            float corr = __expf(m_r[i] - mnew);
            m_r[i] = mnew;
            float rs = p0 + p1;
#pragma unroll
            for (int off = 16; off > 0; off >>= 1)
                rs += __shfl_xor_sync(0xffffffffu, rs, off);
            l_r[i] = l_r[i] * corr + rs;
            o[i].x *= corr; o[i].y *= corr; o[i].z *= corr; o[i].w *= corr;
            Ps[(r0 + i) * 65 + n0] = p0;
            Ps[(r0 + i) * 65 + n1] = p1;
        }
        __syncwarp();

#pragma unroll 2
        for (int n = 0; n < 64; n++) {
            float4 v4 = Vs[n * 32 + lane];
#pragma unroll
            for (int i = 0; i < 8; i++) {
                float p = Ps[(r0 + i) * 65 + n];
                o[i].x = fmaf(p, v4.x, o[i].x);
                o[i].y = fmaf(p, v4.y, o[i].y);
                o[i].z = fmaf(p, v4.z, o[i].z);
                o[i].w = fmaf(p, v4.w, o[i].w);
            }
        }
        __syncthreads();
    }

#pragma unroll
    for (int i = 0; i < 8; i++) {
        float inv = 1.0f / l_r[i];
        float4 r = o[i];
        r.x *= inv; r.y *= inv; r.z *= inv; r.w *= inv;
        *(float4*)(AO + (size_t)(b * SEQ + (qb << 6) + r0 + i) * EMBED
                      + h * HD + (lane << 2)) = r;
    }
}

// ==================== launch ====================
extern "C" void kernel_launch(void* const* d_in, const int* in_sizes, int n_in,
                              void* d_out, int out_size)
{
    const float* x  = (const float*)d_in[0];
    const float* Wq = (const float*)d_in[1];
    const float* bq = (const float*)d_in[2];
    const float* Wk = (const float*)d_in[3];
    const float* bk = (const float*)d_in[4];
    const float* Wv = (const float*)d_in[5];
    const float* bv = (const float*)d_in[6];
    const float* Wo = (const float*)d_in[7];
    const float* bo = (const float*)d_in[8];
    float* out = (float*)d_out;

    float *gq, *gk, *gv, *gao;
    cudaGetSymbolAddress((void**)&gq,  g_Q);
    cudaGetSymbolAddress((void**)&gk,  g_K);
    cudaGetSymbolAddress((void**)&gv,  g_V);
    cudaGetSymbolAddress((void**)&gao, g_AO);

    cudaFuncSetAttribute(gemm_tf32, cudaFuncAttributeMaxDynamicSharedMemorySize,
                         G_SMEM_BYTES);
    cudaFuncSetAttribute(gqa_attn, cudaFuncAttributeMaxDynamicSharedMemorySize,
                         ATT_SMEM_BYTES);

    dim3 blk(256);
    gemm_tf32<<<dim3(EMBED / 128, ROWS_TOTAL / 128), blk, G_SMEM_BYTES>>>(
        x, Wq, bq, gq, EMBED, EMBED);
    gemm_tf32<<<dim3(KVDIM / 128, ROWS_TOTAL / 128), blk, G_SMEM_BYTES>>>(
        x, Wk, bk, gk, KVDIM, EMBED);
    gemm_tf32<<<dim3(KVDIM / 128, ROWS_TOTAL / 128), blk, G_SMEM_BYTES>>>(
        x, Wv, bv, gv, KVDIM, EMBED);

    gqa_attn<<<dim3(SEQ / 64, BATCH * HEADS), blk, ATT_SMEM_BYTES>>>(
        gq, gk, gv, gao);

    gemm_tf32<<<dim3(EMBED / 128, ROWS_TOTAL / 128), blk, G_SMEM_BYTES>>>(
        gao, Wo, bo, out, EMBED, EMBED);
}

// round 8
// speedup vs baseline: 3.4283x; 2.0790x over previous
#include <cuda_runtime.h>
#include <cstdint>

#define EMBED 2048
#define KVDIM 512
#define SEQ   2048
#define BATCH 2
#define ROWS_TOTAL 4096

// -------- scratch (allocation-free: __device__ globals), all tf32-as-u32 ----
__device__ uint32_t g_xt [ROWS_TOTAL * EMBED];
__device__ uint32_t g_Wqt[EMBED * EMBED];
__device__ uint32_t g_Wkt[EMBED * KVDIM];
__device__ uint32_t g_Wvt[EMBED * KVDIM];
__device__ uint32_t g_Wot[EMBED * EMBED];
__device__ uint32_t g_Qt [ROWS_TOTAL * EMBED];
__device__ uint32_t g_Kt [ROWS_TOTAL * KVDIM];
__device__ uint32_t g_Vt [ROWS_TOTAL * KVDIM];
__device__ uint32_t g_AOt[ROWS_TOTAL * EMBED];

__device__ __forceinline__ uint32_t f2tf32(float f) {
    uint32_t u;
    asm("cvt.rna.tf32.f32 %0, %1;" : "=r"(u) : "f"(f));
    return u;
}

__device__ __forceinline__ void mma_tf32(float* c, const uint32_t* a, const uint32_t* b) {
    asm volatile(
        "mma.sync.aligned.m16n8k8.row.col.f32.tf32.tf32.f32 "
        "{%0,%1,%2,%3}, {%4,%5,%6,%7}, {%8,%9}, {%0,%1,%2,%3};"
        : "+f"(c[0]), "+f"(c[1]), "+f"(c[2]), "+f"(c[3])
        : "r"(a[0]), "r"(a[1]), "r"(a[2]), "r"(a[3]), "r"(b[0]), "r"(b[1]));
}

__device__ __forceinline__ void cp_async16(uint32_t saddr, const void* g) {
    asm volatile("cp.async.cg.shared.global [%0], [%1], 16;\n" :: "r"(saddr), "l"(g));
}
__device__ __forceinline__ void cp_commit() { asm volatile("cp.async.commit_group;\n"); }
template<int N> __device__ __forceinline__ void cp_wait() {
    asm volatile("cp.async.wait_group %0;\n" :: "n"(N));
}

// ==================== fp32 -> tf32 conversion (memory-bound) ====================
__global__ void cvt_tf32_kernel(const float* __restrict__ in, uint32_t* __restrict__ out) {
    int i = (blockIdx.x * 256 + threadIdx.x) * 4;
    float4 v = *(const float4*)(in + i);
    uint4 o;
    o.x = f2tf32(v.x); o.y = f2tf32(v.y); o.z = f2tf32(v.z); o.w = f2tf32(v.w);
    *(uint4*)(out + i) = o;
}

// ==================== TF32 GEMM (preconverted inputs, cp.async 3-stage) =========
// 128x128x32 block tile, 256 thr = 8 warps (2m x 4n), warp 64x32, m16n8k8.
// As[128][36] m-major, Bs[32][136] k-major, per stage. 3 stages.
#define GS_A (128 * 36)            // 4608 u32
#define GS_B (32 * 136)            // 4352 u32
#define G_STAGE (GS_A + GS_B)      // 8960 u32
#define G_SMEM_BYTES (3 * G_STAGE * 4)   // 107520 B

__device__ __forceinline__ void gemm_body(
    const uint32_t* __restrict__ A, const uint32_t* __restrict__ B,
    const float* __restrict__ bias, void* __restrict__ Cout,
    int N, int K, int out_tf32, int bm, int bn, uint32_t* sm)
{
    const int tid  = threadIdx.x;
    const int lane = tid & 31;
    const int warp = tid >> 5;
    const int wm   = (warp >> 2) * 64;
    const int wn   = (warp & 3) * 32;
    const int g    = lane >> 2;
    const int tq   = lane & 3;
    const int KT   = K / 32;

    const int a_row = tid >> 3;          // +32*i
    const int a_c4  = (tid & 7) << 2;
    const int b_k   = tid >> 5;          // +8*i
    const int b_n4  = (tid & 31) << 2;

    const uint32_t* aG = A + (size_t)(bm + a_row) * K + a_c4;
    const uint32_t* bG = B + (size_t)b_k * N + bn + b_n4;

    uint32_t sA_base, sB_base;
    {
        uint32_t s0 = (uint32_t)__cvta_generic_to_shared(sm);
        sA_base = s0;
        sB_base = s0 + GS_A * 4;
    }

    float acc[4][4][4];
#pragma unroll
    for (int mt = 0; mt < 4; mt++)
#pragma unroll
        for (int nt = 0; nt < 4; nt++)
#pragma unroll
            for (int i = 0; i < 4; i++) acc[mt][nt][i] = 0.f;

    auto issue = [&](int stage, int kt) {
        uint32_t sa = sA_base + stage * G_STAGE * 4;
        uint32_t sb = sB_base + stage * G_STAGE * 4;
        const uint32_t* ag = aG + kt * 32;
        const uint32_t* bg = bG + (size_t)(kt * 32) * N;
#pragma unroll
        for (int i = 0; i < 4; i++)
            cp_async16(sa + ((a_row + i * 32) * 36 + a_c4) * 4,
                       ag + (size_t)(i * 32) * K);
#pragma unroll
        for (int i = 0; i < 4; i++)
            cp_async16(sb + ((b_k + i * 8) * 136 + b_n4) * 4,
                       bg + (size_t)(i * 8) * N);
    };

    issue(0, 0); cp_commit();
    issue(1, 1); cp_commit();

    for (int kt = 0; kt < KT; kt++) {
        cp_wait<1>();
        __syncthreads();
        if (kt + 2 < KT) issue((kt + 2) % 3, kt + 2);
        cp_commit();

        const uint32_t* Ab = sm + (kt % 3) * G_STAGE + (wm + g) * 36;
        const uint32_t* Bb = sm + (kt % 3) * G_STAGE + GS_A + wn + g;
#pragma unroll
        for (int ks = 0; ks < 4; ks++) {
            uint32_t af[4][4], bf[4][2];
#pragma unroll
            for (int mt = 0; mt < 4; mt++) {
                const uint32_t* p = Ab + mt * 16 * 36 + ks * 8 + tq;
                af[mt][0] = p[0];
                af[mt][1] = p[8 * 36];
                af[mt][2] = p[4];
                af[mt][3] = p[8 * 36 + 4];
            }
#pragma unroll
            for (int nt = 0; nt < 4; nt++) {
                const uint32_t* p = Bb + (ks * 8 + tq) * 136 + nt * 8;
                bf[nt][0] = p[0];
                bf[nt][1] = p[4 * 136];
            }
#pragma unroll
            for (int mt = 0; mt < 4; mt++)
#pragma unroll
                for (int nt = 0; nt < 4; nt++)
                    mma_tf32(acc[mt][nt], af[mt], bf[nt]);
        }
        __syncthreads();
    }

#pragma unroll
    for (int nt = 0; nt < 4; nt++) {
        int n0 = bn + wn + nt * 8 + tq * 2;
        float bv0 = bias[n0], bv1 = bias[n0 + 1];
#pragma unroll
        for (int mt = 0; mt < 4; mt++) {
            int m0 = bm + wm + mt * 16 + g;
            float v00 = acc[mt][nt][0] + bv0, v01 = acc[mt][nt][1] + bv1;
            float v10 = acc[mt][nt][2] + bv0, v11 = acc[mt][nt][3] + bv1;
            if (out_tf32) {
                uint32_t* C = (uint32_t*)Cout;
                *(uint2*)(C + (size_t)m0 * N + n0)       = make_uint2(f2tf32(v00), f2tf32(v01));
                *(uint2*)(C + (size_t)(m0 + 8) * N + n0) = make_uint2(f2tf32(v10), f2tf32(v11));
            } else {
                float* C = (float*)Cout;
                *(float2*)(C + (size_t)m0 * N + n0)       = make_float2(v00, v01);
                *(float2*)(C + (size_t)(m0 + 8) * N + n0) = make_float2(v10, v11);
            }
        }
    }
}

__global__ __launch_bounds__(256) void gemm_tf32(
    const uint32_t* __restrict__ A, const uint32_t* __restrict__ B,
    const float* __restrict__ bias, void* __restrict__ C,
    int N, int K, int out_tf32)
{
    extern __shared__ uint32_t sm[];
    gemm_body(A, B, bias, C, N, K, out_tf32, blockIdx.y * 128, blockIdx.x * 128, sm);
}

__global__ __launch_bounds__(256) void gemm_kv(
    const uint32_t* __restrict__ A,
    const uint32_t* __restrict__ Bk, const float* __restrict__ bk, uint32_t* Ck,
    const uint32_t* __restrict__ Bv, const float* __restrict__ bv, uint32_t* Cv)
{
    extern __shared__ uint32_t sm[];
    const uint32_t* B  = blockIdx.z ? Bv : Bk;
    const float* bias  = blockIdx.z ? bv : bk;
    uint32_t* C        = blockIdx.z ? Cv : Ck;
    gemm_body(A, B, bias, C, KVDIM, EMBED, 1, blockIdx.y * 128, blockIdx.x * 128, sm);
}

// ==================== Flash attention, tf32 mma (causal, GQA) ====================
// 128 thr = 4 warps; q-tile 64 (warp w: rows w*16..+16), k-tile 64, d = 128.
#define A_KS_STRIDE 132
#define A_VS_STRIDE 136
#define A_PS_STRIDE 68
#define A_KS_SIZE (64 * A_KS_STRIDE)
#define A_VS_SIZE (64 * A_VS_STRIDE)
#define A_PS_SIZE (64 * A_PS_STRIDE)
#define ATT_SMEM_BYTES ((A_KS_SIZE + A_VS_SIZE + A_PS_SIZE) * 4)  // 86016 B

__global__ __launch_bounds__(128) void gqa_attn_mma(
    const uint32_t* __restrict__ Qt, const uint32_t* __restrict__ Kt,
    const uint32_t* __restrict__ Vt, uint32_t* __restrict__ AOt)
{
    extern __shared__ uint32_t sm[];
    uint32_t* Ks = sm;
    uint32_t* Vs = sm + A_KS_SIZE;
    uint32_t* Ps = Vs + A_VS_SIZE;

    const int tid  = threadIdx.x;
    const int lane = tid & 31;
    const int warp = tid >> 5;
    const int g    = lane >> 2;
    const int tq   = lane & 3;
    const int qb   = 31 - blockIdx.x;
    const int b    = blockIdx.y >> 4;
    const int h    = blockIdx.y & 15;
    const int grp  = h >> 2;
    const float scale = 0.08838834764831845f;

    // ---- stage Q tile (64 tok x 128 d = 2048 uint4) through Ks ----
    const uint32_t* Qg = Qt + (size_t)(b * SEQ + qb * 64) * EMBED + h * 128;
#pragma unroll
    for (int i = 0; i < 16; i++) {
        int idx = i * 128 + tid;
        int tok = idx >> 5, q4 = (idx & 31) << 2;
        *(uint4*)&Ks[tok * A_KS_STRIDE + q4] =
            *(const uint4*)(Qg + (size_t)tok * EMBED + q4);
    }
    __syncthreads();

    uint32_t qf[16][4];
    {
        const uint32_t* base = Ks + (warp * 16 + g) * A_KS_STRIDE + tq;
#pragma unroll
        for (int ks = 0; ks < 16; ks++) {
            qf[ks][0] = base[ks * 8];
            qf[ks][1] = base[ks * 8 + 8 * A_KS_STRIDE];
            qf[ks][2] = base[ks * 8 + 4];
            qf[ks][3] = base[ks * 8 + 8 * A_KS_STRIDE + 4];
        }
    }
    __syncthreads();

    float oacc[16][4];
#pragma unroll
    for (int nt = 0; nt < 16; nt++)
#pragma unroll
        for (int i = 0; i < 4; i++) oacc[nt][i] = 0.f;

    float m0 = -1e30f, m1 = -1e30f, l0 = 0.f, l1 = 0.f;
    const int rowg = qb * 64 + warp * 16 + g;

    const uint32_t* Kg = Kt + (size_t)(b * SEQ) * KVDIM + grp * 128;
    const uint32_t* Vg = Vt + (size_t)(b * SEQ) * KVDIM + grp * 128;

    for (int kb = 0; kb <= qb; kb++) {
        // ---- load K, V tiles (64 tok x 128 d = 2048 uint4 each) ----
#pragma unroll
        for (int i = 0; i < 16; i++) {
            int idx = i * 128 + tid;
            int tok = idx >> 5, q4 = (idx & 31) << 2;
            size_t go = (size_t)(kb * 64 + tok) * KVDIM + q4;
            *(uint4*)&Ks[tok * A_KS_STRIDE + q4] = *(const uint4*)(Kg + go);
            *(uint4*)&Vs[tok * A_VS_STRIDE + q4] = *(const uint4*)(Vg + go);
        }
        __syncthreads();

        // ---- S = Q K^T ----
        float sacc[8][4];
#pragma unroll
        for (int nt = 0; nt < 8; nt++)
#pragma unroll
            for (int i = 0; i < 4; i++) sacc[nt][i] = 0.f;

#pragma unroll
        for (int ks = 0; ks < 16; ks++) {
            const uint32_t* bp = Ks + g * A_KS_STRIDE + ks * 8 + tq;
#pragma unroll
            for (int nt = 0; nt < 8; nt++) {
                uint32_t bf[2];
                bf[0] = bp[nt * 8 * A_KS_STRIDE];
                bf[1] = bp[nt * 8 * A_KS_STRIDE + 4];
                mma_tf32(sacc[nt], qf[ks], bf);
            }
        }

        // ---- online softmax ----
        const bool diag = (kb == qb);
        const int col0 = kb * 64 + 2 * tq;
        float mx0 = -1e30f, mx1 = -1e30f;
#pragma unroll
        for (int nt = 0; nt < 8; nt++) {
#pragma unroll
            for (int j = 0; j < 2; j++) {
                int col = col0 + nt * 8 + j;
                float v = sacc[nt][j] * scale;
                if (diag && col > rowg) v = -1e30f;
                sacc[nt][j] = v;
                mx0 = fmaxf(mx0, v);
                float w = sacc[nt][2 + j] * scale;
                if (diag && col > rowg + 8) w = -1e30f;
                sacc[nt][2 + j] = w;
                mx1 = fmaxf(mx1, w);
            }
        }
#pragma unroll
        for (int off = 1; off <= 2; off <<= 1) {
            mx0 = fmaxf(mx0, __shfl_xor_sync(0xffffffffu, mx0, off));
            mx1 = fmaxf(mx1, __shfl_xor_sync(0xffffffffu, mx1, off));
        }
        float nm0 = fmaxf(m0, mx0), nm1 = fmaxf(m1, mx1);
        float c0 = __expf(m0 - nm0), c1 = __expf(m1 - nm1);
        m0 = nm0; m1 = nm1;

        float s0 = 0.f, s1 = 0.f;
#pragma unroll
        for (int nt = 0; nt < 8; nt++) {
#pragma unroll
            for (int j = 0; j < 2; j++) {
                float p = __expf(sacc[nt][j] - nm0);
                sacc[nt][j] = p; s0 += p;
                float q = __expf(sacc[nt][2 + j] - nm1);
                sacc[nt][2 + j] = q; s1 += q;
            }
        }
#pragma unroll
        for (int off = 1; off <= 2; off <<= 1) {
            s0 += __shfl_xor_sync(0xffffffffu, s0, off);
            s1 += __shfl_xor_sync(0xffffffffu, s1, off);
        }
        l0 = l0 * c0 + s0;
        l1 = l1 * c1 + s1;
#pragma unroll
        for (int nt = 0; nt < 16; nt++) {
            oacc[nt][0] *= c0; oacc[nt][1] *= c0;
            oacc[nt][2] *= c1; oacc[nt][3] *= c1;
        }

        // ---- P -> smem as tf32 ----
        {
            uint32_t* pp = Ps + (warp * 16 + g) * A_PS_STRIDE + 2 * tq;
#pragma unroll
            for (int nt = 0; nt < 8; nt++) {
                *(uint2*)&pp[nt * 8] =
                    make_uint2(f2tf32(sacc[nt][0]), f2tf32(sacc[nt][1]));
                *(uint2*)&pp[nt * 8 + 8 * A_PS_STRIDE] =
                    make_uint2(f2tf32(sacc[nt][2]), f2tf32(sacc[nt][3]));
            }
        }
        __syncwarp();

        // ---- O += P V ----
#pragma unroll
        for (int ks = 0; ks < 8; ks++) {
            uint32_t af[4];
            const uint32_t* ap = Ps + (warp * 16 + g) * A_PS_STRIDE + ks * 8 + tq;
            af[0] = ap[0];
            af[1] = ap[8 * A_PS_STRIDE];
            af[2] = ap[4];
            af[3] = ap[8 * A_PS_STRIDE + 4];
            const uint32_t* vp = Vs + (ks * 8 + tq) * A_VS_STRIDE + g;
#pragma unroll
            for (int nt = 0; nt < 16; nt++) {
                uint32_t bf[2];
                bf[0] = vp[nt * 8];
                bf[1] = vp[nt * 8 + 4 * A_VS_STRIDE];
                mma_tf32(oacc[nt], af, bf);
            }
        }
        __syncthreads();
    }

    // ---- epilogue: normalize, cvt to tf32, store AO ----
    float inv0 = 1.f / l0, inv1 = 1.f / l1;
    uint32_t* out0 = AOt + (size_t)(b * SEQ + qb * 64 + warp * 16 + g) * EMBED
                         + h * 128 + 2 * tq;
    uint32_t* out1 = out0 + (size_t)8 * EMBED;
#pragma unroll
    for (int nt = 0; nt < 16; nt++) {
        *(uint2*)(out0 + nt * 8) =
            make_uint2(f2tf32(oacc[nt][0] * inv0), f2tf32(oacc[nt][1] * inv0));
        *(uint2*)(out1 + nt * 8) =
            make_uint2(f2tf32(oacc[nt][2] * inv1), f2tf32(oacc[nt][3] * inv1));
    }
}

// ==================== launch ====================
extern "C" void kernel_launch(void* const* d_in, const int* in_sizes, int n_in,
                              void* d_out, int out_size)
{
    const float* x  = (const float*)d_in[0];
    const float* Wq = (const float*)d_in[1];
    const float* bq = (const float*)d_in[2];
    const float* Wk = (const float*)d_in[3];
    const float* bk = (const float*)d_in[4];
    const float* Wv = (const float*)d_in[5];
    const float* bv = (const float*)d_in[6];
    const float* Wo = (const float*)d_in[7];
    const float* bo = (const float*)d_in[8];
    float* out = (float*)d_out;

    uint32_t *xt, *wqt, *wkt, *wvt, *wot, *qt, *kt, *vt, *aot;
    cudaGetSymbolAddress((void**)&xt,  g_xt);
    cudaGetSymbolAddress((void**)&wqt, g_Wqt);
    cudaGetSymbolAddress((void**)&wkt, g_Wkt);
    cudaGetSymbolAddress((void**)&wvt, g_Wvt);
    cudaGetSymbolAddress((void**)&wot, g_Wot);
    cudaGetSymbolAddress((void**)&qt,  g_Qt);
    cudaGetSymbolAddress((void**)&kt,  g_Kt);
    cudaGetSymbolAddress((void**)&vt,  g_Vt);
    cudaGetSymbolAddress((void**)&aot, g_AOt);

    cudaFuncSetAttribute(gemm_tf32, cudaFuncAttributeMaxDynamicSharedMemorySize,
                         G_SMEM_BYTES);
    cudaFuncSetAttribute(gemm_kv, cudaFuncAttributeMaxDynamicSharedMemorySize,
                         G_SMEM_BYTES);
    cudaFuncSetAttribute(gqa_attn_mma, cudaFuncAttributeMaxDynamicSharedMemorySize,
                         ATT_SMEM_BYTES);

    cvt_tf32_kernel<<<ROWS_TOTAL * EMBED / 1024, 256>>>(x,  xt);
    cvt_tf32_kernel<<<EMBED * EMBED / 1024, 256>>>(Wq, wqt);
    cvt_tf32_kernel<<<EMBED * KVDIM / 1024, 256>>>(Wk, wkt);
    cvt_tf32_kernel<<<EMBED * KVDIM / 1024, 256>>>(Wv, wvt);
    cvt_tf32_kernel<<<EMBED * EMBED / 1024, 256>>>(Wo, wot);

    dim3 blk(256);
    gemm_tf32<<<dim3(EMBED / 128, ROWS_TOTAL / 128), blk, G_SMEM_BYTES>>>(
        xt, wqt, bq, qt, EMBED, EMBED, 1);
    gemm_kv<<<dim3(KVDIM / 128, ROWS_TOTAL / 128, 2), blk, G_SMEM_BYTES>>>(
        xt, wkt, bk, kt, wvt, bv, vt);

    gqa_attn_mma<<<dim3(SEQ / 64, BATCH * 16), dim3(128), ATT_SMEM_BYTES>>>(
        qt, kt, vt, aot);

    gemm_tf32<<<dim3(EMBED / 128, ROWS_TOTAL / 128), blk, G_SMEM_BYTES>>>(
        aot, wot, bo, out, EMBED, EMBED, 0);
}